// round 12
// baseline (speedup 1.0000x reference)
#include <cuda_runtime.h>
#include <cstdint>

// EMA scan: y_t = d*x_t + (1-d)*y_{t-1}, y_{-1} = x[0], d = 0.9 (a = 0.1).
//
// Persistent warps + per-warp cp.async (LDGSTS) pipeline:
//  - Each warp: 512-element segments (4 rows x 32 lanes x float4).
//  - Prefetch goes to SMEM via cp.async.cg, not registers -> low regs,
//    6 CTAs/SM, deep MLP at zero register cost.
//  - Each lane fetches exactly the bytes it later reads (own row chunks +
//    own halo slice) -> per-thread wait_group ordering suffices: zero
//    barriers, zero syncwarp, warps fully independent.
//  - Lookback 16 elements (a^16 = 1e-16 << fp32 eps): Kogge-Stone {1,2}.
//  - Row carry_out = lane-31 inclusive value (independent of carry_in).
//  - Stores: __stcs (evict-first streaming; proven best in R8 A/B).
//  - R10 crash fix: halo LDS is guarded by (lane < 4) — the halo region is
//    only 16 floats; unguarded lane-31 read walked off the buffer.

#define NT      256
#define NW      (NT / 32)
#define ROWS    4
#define ROWE    128                  // elements per row
#define WREG    (ROWS * ROWE)        // 512 elements per warp-segment
#define TILE    (NW * WREG)          // 4096 elements per block-segment
#define STAGES  2
#define SSTRIDE (WREG + 16)          // 528 floats: 512 data + 16 halo

__device__ __forceinline__ void cp16(uint32_t saddr, const float* g) {
    asm volatile("cp.async.cg.shared.global [%0], [%1], 16;"
                 :: "r"(saddr), "l"(g));
}
__device__ __forceinline__ void cp_commit() {
    asm volatile("cp.async.commit_group;");
}
template <int N>
__device__ __forceinline__ void cp_wait() {
    asm volatile("cp.async.wait_group %0;" :: "n"(N));
}

__device__ __forceinline__ float horner4(float a, float4 w) {
    float h = w.x;
    h = fmaf(a, h, w.y);
    h = fmaf(a, h, w.z);
    h = fmaf(a, h, w.w);
    return h;
}

__global__ __launch_bounds__(NT, 6)
void ema_kernel(const float* __restrict__ x,
                const float* __restrict__ decay_p,
                float* __restrict__ out, int n, int nseg)
{
    __shared__ __align__(16) float buf[NW * STAGES * SSTRIDE];  // 33.8 KB

    const float d  = __ldg(decay_p);
    const float a  = 1.0f - d;
    const float a2 = a * a;
    const float p4 = a2 * a2;
    const float p8 = p4 * p4;

    const int lane   = threadIdx.x & 31;
    const int wid    = threadIdx.x >> 5;
    const int stride = gridDim.x;

    // per-lane carry factor a^(4*lane), truncated to 0 for lane >= 4
    float f = 0.0f;
    if (lane < 4)
        f = ((lane & 1) ? p4 : 1.0f) * ((lane & 2) ? p8 : 1.0f);

    float* wbuf0 = &buf[(wid * STAGES + 0) * SSTRIDE];
    float* wbuf1 = &buf[(wid * STAGES + 1) * SSTRIDE];

    // ---- fill stage: each lane cp.asyncs its own 4 row-chunks + halo ----
    auto fill = [&](int wbase, float* wb) -> bool {
        if (wbase + WREG > n) return false;          // tail: direct-gmem path
        uint32_t sb = (uint32_t)__cvta_generic_to_shared(wb);
        #pragma unroll
        for (int r = 0; r < ROWS; r++)
            cp16(sb + (r * ROWE + lane * 4) * 4,
                 x + wbase + r * ROWE + lane * 4);
        if (wbase != 0 && lane < 4)
            cp16(sb + (WREG + lane * 4) * 4, x + wbase - 16 + lane * 4);
        return true;
    };

    // ---- compute + store one segment ----
    auto process = [&](int wbase, const float* wb, bool in_smem) {
        if (wbase >= n) return;
        const bool full = (wbase + WREG <= n);

        float4 v[ROWS];
        float4 hv = make_float4(0.f, 0.f, 0.f, 0.f);
        if (in_smem) {
            #pragma unroll
            for (int r = 0; r < ROWS; r++)
                v[r] = *reinterpret_cast<const float4*>(
                           wb + r * ROWE + lane * 4);
            if (wbase != 0 && lane < 4)      // halo region is only 16 floats
                hv = *reinterpret_cast<const float4*>(wb + WREG + lane * 4);
        } else {
            if (wbase != 0 && lane < 4)
                hv = *reinterpret_cast<const float4*>(x + wbase - 16 + 4 * lane);
            #pragma unroll
            for (int r = 0; r < ROWS; r++) {
                int g = wbase + r * ROWE + 4 * lane;
                v[r].x = (g + 0 < n) ? x[g + 0] : 0.0f;
                v[r].y = (g + 1 < n) ? x[g + 1] : 0.0f;
                v[r].z = (g + 2 < n) ? x[g + 2] : 0.0f;
                v[r].w = (g + 3 < n) ? x[g + 3] : 0.0f;
            }
        }

        // warp seed from the 16-element halo (lanes 0-3 hold data)
        float cw;
        if (wbase == 0) {
            cw = __ldg(x);                           // exact: y_{-1} = x[0]
        } else {
            float hS = 0.0f;
            if (lane < 4) {
                float4 w = make_float4(d * hv.x, d * hv.y, d * hv.z, d * hv.w);
                hS = horner4(a, w);
            }
            float m;
            m = __shfl_up_sync(0xffffffffu, hS, 1);
            if (lane >= 1) hS = fmaf(p4, m, hS);
            m = __shfl_up_sync(0xffffffffu, hS, 2);
            if (lane >= 2) hS = fmaf(p8, m, hS);
            cw = __shfl_sync(0xffffffffu, hS, 3);
        }

        #pragma unroll
        for (int r = 0; r < ROWS; r++) {
            float4 w = make_float4(d * v[r].x, d * v[r].y,
                                   d * v[r].z, d * v[r].w);
            float S = horner4(a, w);
            float t;
            t = __shfl_up_sync(0xffffffffu, S, 1);
            if (lane >= 1) S = fmaf(p4, t, S);
            t = __shfl_up_sync(0xffffffffu, S, 2);
            if (lane >= 2) S = fmaf(p8, t, S);
            // S covers lanes r-3..r (16 elements) — full required lookback.

            float E = __shfl_up_sync(0xffffffffu, S, 1);
            if (lane == 0) E = 0.0f;
            float c = fmaf(f, cw, E);

            float y0 = fmaf(a, c,  w.x);
            float y1 = fmaf(a, y0, w.y);
            float y2 = fmaf(a, y1, w.z);
            float y3 = fmaf(a, y2, w.w);

            cw = __shfl_sync(0xffffffffu, S, 31);

            int g = wbase + r * ROWE + 4 * lane;
            if (full) {
                __stcs(reinterpret_cast<float4*>(out + g),
                       make_float4(y0, y1, y2, y3));
            } else {
                if (g + 0 < n) out[g + 0] = y0;
                if (g + 1 < n) out[g + 1] = y1;
                if (g + 2 < n) out[g + 2] = y2;
                if (g + 3 < n) out[g + 3] = y3;
            }
        }
    };

    int seg = blockIdx.x;
    if (seg >= nseg) return;

    int  wbase   = seg * TILE + wid * WREG;
    bool cur_sm  = fill(wbase, wbuf0);
    if (cur_sm) cp_commit();
    int  s = 0;

    for (;;) {
        const int  seg2      = seg + stride;
        const bool have_next = (seg2 < nseg);

        bool next_sm = false;
        int  wbase2  = 0;
        if (have_next) {
            wbase2  = seg2 * TILE + wid * WREG;
            next_sm = fill(wbase2, (s == 0) ? wbuf1 : wbuf0);
            if (next_sm) cp_commit();
        }

        if (cur_sm) {
            if (next_sm) cp_wait<1>();   // cur's group complete, next in flight
            else         cp_wait<0>();   // drain everything
        }

        process(wbase, (s == 0) ? wbuf0 : wbuf1, cur_sm);

        if (!have_next) break;
        seg    = seg2;
        wbase  = wbase2;
        cur_sm = next_sm;
        s ^= 1;
    }
}

extern "C" void kernel_launch(void* const* d_in, const int* in_sizes, int n_in,
                              void* d_out, int out_size)
{
    const float* x     = (const float*)d_in[0];
    const float* decay = (const float*)d_in[1];
    float*       out   = (float*)d_out;
    const int    n     = in_sizes[0];

    const int nseg = (n + TILE - 1) / TILE;
    int grid = 148 * 6;                 // persistent: 6 CTAs/SM on 148 SMs
    if (grid > nseg) grid = nseg;
    ema_kernel<<<grid, NT>>>(x, decay, out, n, nseg);
}